// round 16
// baseline (speedup 1.0000x reference)
#include <cuda_runtime.h>
#include <cuda_fp16.h>
#include <cstdint>
#include <math.h>

#define BB 2
#define TT 2048
#define DD 1024
#define HH 16
#define HDIM 64
#define MROWS (BB * TT)   // 4096

// ---------------------------------------------------------------------------
// Scratch (device globals; no allocation anywhere). All fp16 single-pass.
// ---------------------------------------------------------------------------
__device__ __align__(256) __half g_x16[(size_t)MROWS * DD];
__device__ __align__(256) __half g_wq16[(size_t)3 * DD * DD];
__device__ __align__(256) __half g_wp16[(size_t)DD * DD];
__device__ __align__(256) __half g_y16[(size_t)MROWS * DD];
__device__ __align__(256) __half g_q16[(size_t)MROWS * DD];
__device__ __align__(256) __half g_k16[(size_t)MROWS * DD];
__device__ __align__(256) __half g_v16[(size_t)MROWS * DD];

// ---------------------------------------------------------------------------
// helpers
// ---------------------------------------------------------------------------
__device__ __forceinline__ uint32_t smem_u32(const void* p) {
    uint32_t a;
    asm("{ .reg .u64 t; cvta.to.shared.u64 t, %1; cvt.u32.u64 %0, t; }"
        : "=r"(a) : "l"(p));
    return a;
}
__device__ __forceinline__ void cp16(uint32_t d, const void* g) {
    asm volatile("cp.async.cg.shared.global [%0], [%1], 16;" :: "r"(d), "l"(g));
}
__device__ __forceinline__ void ldsm4(uint32_t* r, uint32_t a) {
    asm volatile("ldmatrix.sync.aligned.m8n8.x4.shared.b16 {%0,%1,%2,%3}, [%4];"
        : "=r"(r[0]), "=r"(r[1]), "=r"(r[2]), "=r"(r[3]) : "r"(a));
}
__device__ __forceinline__ void ldsm4t(uint32_t* r, uint32_t a) {
    asm volatile("ldmatrix.sync.aligned.m8n8.x4.trans.shared.b16 {%0,%1,%2,%3}, [%4];"
        : "=r"(r[0]), "=r"(r[1]), "=r"(r[2]), "=r"(r[3]) : "r"(a));
}
// fp32-accumulate HMMA (attention)
__device__ __forceinline__ void mma16816(float* c, const uint32_t* a, const uint32_t* b) {
    asm volatile("mma.sync.aligned.m16n8k16.row.col.f32.f16.f16.f32 "
        "{%0,%1,%2,%3}, {%4,%5,%6,%7}, {%8,%9}, {%0,%1,%2,%3};"
        : "+f"(c[0]), "+f"(c[1]), "+f"(c[2]), "+f"(c[3])
        : "r"(a[0]), "r"(a[1]), "r"(a[2]), "r"(a[3]), "r"(b[0]), "r"(b[1]));
}
// fp16-accumulate HMMA (GEMMs; 2x tensor rate)
__device__ __forceinline__ void mma16816h(uint32_t* c, const uint32_t* a, const uint32_t* b) {
    asm volatile("mma.sync.aligned.m16n8k16.row.col.f16.f16.f16.f16 "
        "{%0,%1}, {%2,%3,%4,%5}, {%6,%7}, {%0,%1};"
        : "+r"(c[0]), "+r"(c[1])
        : "r"(a[0]), "r"(a[1]), "r"(a[2]), "r"(a[3]), "r"(b[0]), "r"(b[1]));
}
__device__ __forceinline__ uint32_t h2pack(float a, float b) {
    __half2 h = __floats2half2_rn(a, b);
    return *(uint32_t*)&h;
}
__device__ __forceinline__ float ex2(float x) {
    float r; asm("ex2.approx.f32 %0, %1;" : "=f"(r) : "f"(x)); return r;
}
#define CP_COMMIT() asm volatile("cp.async.commit_group;" ::: "memory")
#define CP_WAIT1()  asm volatile("cp.async.wait_group 1;" ::: "memory")
#define CP_WAIT3()  asm volatile("cp.async.wait_group 3;" ::: "memory")

// ---------------------------------------------------------------------------
// fused fp32 -> fp16 convert for x, w_qkv, w_proj in one launch
// ---------------------------------------------------------------------------
__global__ __launch_bounds__(256) void convert3_kernel(
    const float* __restrict__ i0, __half* __restrict__ o0, int n0,
    const float* __restrict__ i1, __half* __restrict__ o1, int n1,
    const float* __restrict__ i2, __half* __restrict__ o2, int n2) {
    int i = blockIdx.x * blockDim.x + threadIdx.x;
    const float* in; __half* out; int j;
    if (i < n0) { in = i0; out = o0; j = i; }
    else if (i < n0 + n1) { in = i1; out = o1; j = i - n0; }
    else if (i < n0 + n1 + n2) { in = i2; out = o2; j = i - n0 - n1; }
    else return;
    float4 v = ((const float4*)in)[j];
    ((uint32_t*)out)[2 * j]     = h2pack(v.x, v.y);
    ((uint32_t*)out)[2 * j + 1] = h2pack(v.z, v.w);
}

// ---------------------------------------------------------------------------
// fp16 GEMM, fp16-acc HMMA with per-BK=32 fp32 promotion.
// BK=32 stages, 2-rows-per-144B packed pitch, 6-slot ring, 4 in flight,
// barrier every other iteration. 110.6KB/CTA, 2 CTA/SM, 32 iterations.
// ---------------------------------------------------------------------------
#define GTILE2 (64 * 144)        // 9216
#define GSTAGE2 (2 * GTILE2)     // 18432
#define GSLOTS 6
#define GSMEM (GSLOTS * GSTAGE2) // 110592
#define GNIT2 32

__device__ __forceinline__ uint32_t g_off(int row, int ch) {
    return (uint32_t)((row >> 1) * 144 + (row & 1) * 64 + ch * 16);
}

__device__ __forceinline__ void load_stage2(uint32_t st,
                                            const __half* __restrict__ A,
                                            const __half* __restrict__ B,
                                            int m0, int n0, int kk, int tid) {
    #pragma unroll
    for (int t = 0; t < 2; t++) {
        const int idx = tid + t * 256;
        const int row = idx >> 2;
        const int ch  = idx & 3;
        const uint32_t off = g_off(row, ch);
        cp16(st + off,          A + (size_t)(m0 + row) * DD + kk + ch * 8);
        cp16(st + GTILE2 + off, B + (size_t)(n0 + row) * DD + kk + ch * 8);
    }
}

__device__ __forceinline__ void gemm_mainloop(uint32_t sbase,
                                              const __half* __restrict__ A,
                                              const __half* __restrict__ B,
                                              int m0, int n0, int tid,
                                              float (&acc)[2][8][4]) {
    const int lane = tid & 31;
    const int warp = tid >> 5;
    const int wm = warp >> 1;
    const int wn = warp & 1;
    const int l_sub = lane & 15;
    const int l_cc  = lane >> 4;

    #pragma unroll
    for (int s = 0; s < 4; s++) {
        load_stage2(sbase + s * GSTAGE2, A, B, m0, n0, s * 32, tid);
        CP_COMMIT();
    }

    int slot = 0;
    for (int it = 0; it < GNIT2; it++) {
        CP_WAIT3();
        if ((it & 1) == 0) __syncthreads();

        if (it + 4 < GNIT2) {
            int ns = slot + 4; if (ns >= GSLOTS) ns -= GSLOTS;
            load_stage2(sbase + ns * GSTAGE2, A, B, m0, n0, (it + 4) * 32, tid);
        }
        CP_COMMIT();

        const uint32_t st = sbase + slot * GSTAGE2;

        // fp16 accumulators for this BK=32 group
        uint32_t hacc[2][8][2];
        #pragma unroll
        for (int i = 0; i < 2; i++)
            #pragma unroll
            for (int j = 0; j < 8; j++) { hacc[i][j][0] = 0u; hacc[i][j][1] = 0u; }

        #pragma unroll
        for (int h = 0; h < 2; h++) {
            const int cc = h * 2 + l_cc;
            uint32_t a[2][4];
            #pragma unroll
            for (int i = 0; i < 2; i++)
                ldsm4(a[i], st + g_off(wm * 32 + i * 16 + l_sub, cc));
            #pragma unroll
            for (int j2 = 0; j2 < 4; j2++) {
                uint32_t r[4];
                ldsm4(r, st + GTILE2 + g_off(wn * 64 + j2 * 16 + l_sub, cc));
                uint32_t b0[2] = {r[0], r[2]};
                uint32_t b1[2] = {r[1], r[3]};
                #pragma unroll
                for (int i = 0; i < 2; i++) {
                    mma16816h(hacc[i][j2 * 2],     a[i], b0);
                    mma16816h(hacc[i][j2 * 2 + 1], a[i], b1);
                }
            }
        }

        // promote K=32 partials into fp32 accumulators
        #pragma unroll
        for (int i = 0; i < 2; i++)
            #pragma unroll
            for (int j = 0; j < 8; j++) {
                const float2 f0 = __half22float2(*(__half2*)&hacc[i][j][0]);
                const float2 f1 = __half22float2(*(__half2*)&hacc[i][j][1]);
                acc[i][j][0] += f0.x; acc[i][j][1] += f0.y;
                acc[i][j][2] += f1.x; acc[i][j][3] += f1.y;
            }

        slot = (slot + 1 == GSLOTS) ? 0 : slot + 1;
    }
}

// ---- qkv GEMM: scatter epilogue -> q/k/v fp16 in [b,h,t,d] ----
// q pre-scaled by 0.125 * log2(e) so attention can use ex2 directly.
__global__ __launch_bounds__(256, 2)
void qkv_gemm_kernel(const __half* __restrict__ A,
                     const __half* __restrict__ B,
                     const float* __restrict__ bias,
                     __half* __restrict__ q16, __half* __restrict__ k16,
                     __half* __restrict__ v16) {
    extern __shared__ __align__(1024) char sm[];
    const uint32_t sbase = smem_u32(sm);
    const int tid = threadIdx.x;
    const int lane = tid & 31;
    const int warp = tid >> 5;
    const int wm = warp >> 1, wn = warp & 1;
    const int m0 = blockIdx.y * 128;
    const int n0 = blockIdx.x * 128;

    float acc[2][8][4];
    #pragma unroll
    for (int i = 0; i < 2; i++)
        #pragma unroll
        for (int j = 0; j < 8; j++)
            #pragma unroll
            for (int r = 0; r < 4; r++) acc[i][j][r] = 0.f;

    gemm_mainloop(sbase, A, B, m0, n0, tid, acc);

    const float QSCALE = 0.125f * 1.4426950408889634f;
    const int l4 = lane >> 2;
    const int l2 = (lane & 3) << 1;
    #pragma unroll
    for (int i = 0; i < 2; i++) {
        const int row = m0 + wm * 32 + i * 16 + l4;
        const int bi = row >> 11;
        const int t  = row & 2047;
        #pragma unroll
        for (int j = 0; j < 8; j++) {
            const int col = n0 + wn * 64 + j * 8 + l2;
            const int type = col >> 10;
            const int hc = (col & 1023) >> 6;
            const int d  = col & 63;
            const float2 bv = *(const float2*)(bias + col);
            float v0 = acc[i][j][0] + bv.x, v1 = acc[i][j][1] + bv.y;
            float v2 = acc[i][j][2] + bv.x, v3 = acc[i][j][3] + bv.y;
            if (type == 0) { v0 *= QSCALE; v1 *= QSCALE; v2 *= QSCALE; v3 *= QSCALE; }
            __half* dst = (type == 0) ? q16 : (type == 1) ? k16 : v16;
            const size_t off0 = (((size_t)(bi * HH + hc)) * TT + t) * 64 + d;
            const size_t off1 = off0 + 8 * 64;
            ((uint32_t*)dst)[off0 >> 1] = h2pack(v0, v1);
            ((uint32_t*)dst)[off1 >> 1] = h2pack(v2, v3);
        }
    }
}

// ---- proj GEMM: fp32 epilogue ----
__global__ __launch_bounds__(256, 2)
void proj_gemm_kernel(const __half* __restrict__ A,
                      const __half* __restrict__ B,
                      const float* __restrict__ bias,
                      float* __restrict__ C, int ldc) {
    extern __shared__ __align__(1024) char sm[];
    const uint32_t sbase = smem_u32(sm);
    const int tid = threadIdx.x;
    const int lane = tid & 31;
    const int warp = tid >> 5;
    const int wm = warp >> 1, wn = warp & 1;
    const int m0 = blockIdx.y * 128;
    const int n0 = blockIdx.x * 128;

    float acc[2][8][4];
    #pragma unroll
    for (int i = 0; i < 2; i++)
        #pragma unroll
        for (int j = 0; j < 8; j++)
            #pragma unroll
            for (int r = 0; r < 4; r++) acc[i][j][r] = 0.f;

    gemm_mainloop(sbase, A, B, m0, n0, tid, acc);

    const int l4 = lane >> 2;
    const int l2 = (lane & 3) << 1;
    #pragma unroll
    for (int i = 0; i < 2; i++) {
        const int row0 = m0 + wm * 32 + i * 16 + l4;
        #pragma unroll
        for (int j = 0; j < 8; j++) {
            const int col = n0 + wn * 64 + j * 8 + l2;
            const float2 bv = *(const float2*)(bias + col);
            float2 v0, v1;
            v0.x = acc[i][j][0] + bv.x; v0.y = acc[i][j][1] + bv.y;
            v1.x = acc[i][j][2] + bv.x; v1.y = acc[i][j][3] + bv.y;
            *(float2*)(C + (size_t)row0 * ldc + col) = v0;
            *(float2*)(C + (size_t)(row0 + 8) * ldc + col) = v1;
        }
    }
}

// ---------------------------------------------------------------------------
// Flash attention (R15-validated; fp32-acc, reversed qi, 128-row kv stages,
// ex2 softmax). smem 92.2KB -> 2 CTA/SM.
// ---------------------------------------------------------------------------
#define AP 144
#define Q_BYTES (128 * AP)
#define K128_B (128 * AP)
#define KV_STAGE_B (2 * K128_B)
#define ATT_SMEM (Q_BYTES + 2 * KV_STAGE_B)

__global__ __launch_bounds__(256, 2)
void attn_mma_kernel(const __half* __restrict__ q16, const __half* __restrict__ k16,
                     const __half* __restrict__ v16, __half* __restrict__ y16) {
    extern __shared__ __align__(1024) char sm[];
    const uint32_t sb = smem_u32(sm);

    const int qi = (int)gridDim.x - 1 - (int)blockIdx.x;
    const int h  = blockIdx.y;
    const int b  = blockIdx.z;
    const int q0 = qi * 128;
    const size_t base = ((size_t)(b * HH + h)) * TT * 64;

    const int tid  = threadIdx.x;
    const int warp = tid >> 5;
    const int lane = tid & 31;
    const int l_sub = lane & 15;
    const int l_cc  = lane >> 4;
    const int lq = lane >> 2;
    const int lr = lane & 3;

    const int ntt = qi + 1;
    auto load_kv = [&](int s, int k0) {
        const uint32_t st = sb + Q_BYTES + s * KV_STAGE_B;
        const size_t srcb = base + (size_t)k0 * 64;
        #pragma unroll
        for (int t2 = 0; t2 < 4; t2++) {
            const int idx = tid + t2 * 256;
            const int row = idx >> 3, ch = idx & 7;
            const uint32_t off = row * AP + ch * 16;
            const size_t g = srcb + (size_t)row * 64 + ch * 8;
            cp16(st + off, k16 + g);
            cp16(st + K128_B + off, v16 + g);
        }
    };

    #pragma unroll
    for (int t2 = 0; t2 < 4; t2++) {
        const int idx = tid + t2 * 256;
        const int row = idx >> 3, ch = idx & 7;
        cp16(sb + row * AP + ch * 16, q16 + base + (size_t)(q0 + row) * 64 + ch * 8);
    }
    load_kv(0, 0);
    CP_COMMIT();
    if (ntt > 1) load_kv(1, 128);
    CP_COMMIT();

    CP_WAIT1();
    __syncthreads();

    uint32_t aq[4][4];
    #pragma unroll
    for (int kk = 0; kk < 4; kk++)
        ldsm4(aq[kk], sb + (warp * 16 + l_sub) * AP + (kk * 2 + l_cc) * 16);

    float m0r = -1e30f, m1r = -1e30f, l0 = 0.f, l1 = 0.f;
    float o[8][4];
    #pragma unroll
    for (int j = 0; j < 8; j++)
        #pragma unroll
        for (int r = 0; r < 4; r++) o[j][r] = 0.f;

    const int r0g = q0 + warp * 16 + lq;
    const int r1g = r0g + 8;
    const int rowmaxw = q0 + warp * 16 + 15;

    for (int kt = 0; kt < ntt; kt++) {
        if (kt > 0) {
            CP_WAIT1();
            __syncthreads();
        }
        const uint32_t stg = sb + Q_BYTES + (kt & 1) * KV_STAGE_B;

        #pragma unroll
        for (int sub = 0; sub < 2; sub++) {
            const int k0 = kt * 128 + sub * 64;
            if (k0 > rowmaxw) continue;
            const uint32_t stK = stg + sub * 64 * AP;
            const uint32_t stV = stg + K128_B + sub * 64 * AP;

            float s[8][4];
            #pragma unroll
            for (int j = 0; j < 8; j++)
                #pragma unroll
                for (int r = 0; r < 4; r++) s[j][r] = 0.f;

            #pragma unroll
            for (int kk = 0; kk < 4; kk++) {
                uint32_t bk[8][2];
                #pragma unroll
                for (int j2 = 0; j2 < 4; j2++) {
                    uint32_t r[4];
                    ldsm4(r, stK + (j2 * 16 + l_sub) * AP + (kk * 2 + l_cc) * 16);
                    bk[j2 * 2][0] = r[0];     bk[j2 * 2][1] = r[2];
                    bk[j2 * 2 + 1][0] = r[1]; bk[j2 * 2 + 1][1] = r[3];
                }
                #pragma unroll
                for (int j = 0; j < 8; j++) mma16816(s[j], aq[kk], bk[j]);
            }

            if (k0 + 63 > q0 + warp * 16) {
                #pragma unroll
                for (int j = 0; j < 8; j++) {
                    const int c = k0 + 8 * j + 2 * lr;
                    if (c > r0g)     s[j][0] = -1e30f;
                    if (c + 1 > r0g) s[j][1] = -1e30f;
                    if (c > r1g)     s[j][2] = -1e30f;
                    if (c + 1 > r1g) s[j][3] = -1e30f;
                }
            }

            float mx0 = -1e30f, mx1 = -1e30f;
            #pragma unroll
            for (int j = 0; j < 8; j++) {
                mx0 = fmaxf(mx0, fmaxf(s[j][0], s[j][1]));
                mx1 = fmaxf(mx1, fmaxf(s[j][2], s[j][3]));
            }
            #pragma unroll
            for (int off = 1; off <= 2; off <<= 1) {
                mx0 = fmaxf(mx0, __shfl_xor_sync(0xffffffffu, mx0, off));
                mx1 = fmaxf(mx1, __shfl_xor_sync(0xffffffffu, mx1, off));
            }
            const float mn0 = fmaxf(m0r, mx0), mn1 = fmaxf(m1r, mx1);
            const float c0 = ex2(m0r - mn0), c1 = ex2(m1r - mn1);
            m0r = mn0; m1r = mn1;

            float rs0 = 0.f, rs1 = 0.f;
            #pragma unroll
            for (int j = 0; j < 8; j++) {
                s[j][0] = ex2(s[j][0] - mn0);
                s[j][1] = ex2(s[j][1] - mn0);
                s[j][2] = ex2(s[j][2] - mn1);
                s[j][3] = ex2(s[j][3] - mn1);
                rs0 += s[j][0] + s[j][1];
                rs1 += s[j][2] + s[j][3];
            }
            #pragma unroll
            for (int off = 1; off <= 2; off <<= 1) {
                rs0 += __shfl_xor_sync(0xffffffffu, rs0, off);
                rs1 += __shfl_xor_sync(0xffffffffu, rs1, off);
            }
            l0 = l0 * c0 + rs0;
            l1 = l1 * c1 + rs1;
            #pragma unroll
            for (int j = 0; j < 8; j++) {
                o[j][0] *= c0; o[j][1] *= c0;
                o[j][2] *= c1; o[j][3] *= c1;
            }

            #pragma unroll
            for (int kg = 0; kg < 4; kg++) {
                uint32_t ap[4];
                ap[0] = h2pack(s[2 * kg][0], s[2 * kg][1]);
                ap[1] = h2pack(s[2 * kg][2], s[2 * kg][3]);
                ap[2] = h2pack(s[2 * kg + 1][0], s[2 * kg + 1][1]);
                ap[3] = h2pack(s[2 * kg + 1][2], s[2 * kg + 1][3]);

                const int mm = lane >> 3;
                const int rowv = kg * 16 + (mm & 1) * 8 + (lane & 7);
                const int chb = mm >> 1;

                uint32_t bv[8][2];
                #pragma unroll
                for (int dg = 0; dg < 4; dg++) {
                    uint32_t r[4];
                    ldsm4t(r, stV + rowv * AP + (dg * 2 + chb) * 16);
                    bv[dg * 2][0] = r[0];     bv[dg * 2][1] = r[1];
                    bv[dg * 2 + 1][0] = r[2]; bv[dg * 2 + 1][1] = r[3];
                }
                #pragma unroll
                for (int jn = 0; jn < 8; jn++) mma16816(o[jn], ap, bv[jn]);
            }
        }

        __syncthreads();
        if (kt + 2 < ntt) load_kv(kt & 1, (kt + 2) * 128);
        CP_COMMIT();
    }

    const float inv0 = 1.0f / l0;
    const float inv1 = 1.0f / l1;
    const size_t tok0 = (size_t)(b * TT + q0 + warp * 16 + lq);
    const size_t tok1 = tok0 + 8;
    #pragma unroll
    for (int jn = 0; jn < 8; jn++) {
        const int d = 8 * jn + 2 * lr;
        ((uint32_t*)y16)[(tok0 * DD + h * 64 + d) >> 1] = h2pack(o[jn][0] * inv0, o[jn][1] * inv0);
        ((uint32_t*)y16)[(tok1 * DD + h * 64 + d) >> 1] = h2pack(o[jn][2] * inv1, o[jn][3] * inv1);
    }
}

// ---------------------------------------------------------------------------
// Host side
// ---------------------------------------------------------------------------
extern "C" void kernel_launch(void* const* d_in, const int* in_sizes, int n_in,
                              void* d_out, int out_size) {
    const float* x      = (const float*)d_in[0];
    const float* w_qkv  = (const float*)d_in[2];
    const float* b_qkv  = (const float*)d_in[3];
    const float* w_proj = (const float*)d_in[4];
    const float* b_proj = (const float*)d_in[5];
    float* out = (float*)d_out;

    void *px, *pwq, *pwp, *py, *pq, *pk, *pv;
    cudaGetSymbolAddress(&px, g_x16);
    cudaGetSymbolAddress(&pwq, g_wq16);
    cudaGetSymbolAddress(&pwp, g_wp16);
    cudaGetSymbolAddress(&py, g_y16);
    cudaGetSymbolAddress(&pq, g_q16);
    cudaGetSymbolAddress(&pk, g_k16);
    cudaGetSymbolAddress(&pv, g_v16);

    static int attr_set = 0;
    if (!attr_set) {
        cudaFuncSetAttribute(qkv_gemm_kernel,
                             cudaFuncAttributeMaxDynamicSharedMemorySize, GSMEM);
        cudaFuncSetAttribute(proj_gemm_kernel,
                             cudaFuncAttributeMaxDynamicSharedMemorySize, GSMEM);
        cudaFuncSetAttribute(attn_mma_kernel,
                             cudaFuncAttributeMaxDynamicSharedMemorySize, ATT_SMEM);
        attr_set = 1;
    }

    // 1) fused convert: x, w_qkv, w_proj -> fp16 (one launch)
    {
        const int n0 = (MROWS * DD) / 4;
        const int n1 = (3 * DD * DD) / 4;
        const int n2 = (DD * DD) / 4;
        const int total = n0 + n1 + n2;
        convert3_kernel<<<(total + 255) / 256, 256>>>(
            x, (__half*)px, n0, w_qkv, (__half*)pwq, n1, w_proj, (__half*)pwp, n2);
    }

    // 2) QKV GEMM -> q/k/v fp16 in [b,h,t,d] (q pre-scaled by log2e/8)
    {
        dim3 grid((3 * DD) / 128, MROWS / 128);
        qkv_gemm_kernel<<<grid, 256, GSMEM>>>(
            (const __half*)px, (const __half*)pwq, b_qkv,
            (__half*)pq, (__half*)pk, (__half*)pv);
    }

    // 3) flash attention (mma.sync fp16, reversed qi) -> y fp16
    {
        dim3 grid(TT / 128, HH, BB);
        attn_mma_kernel<<<grid, 256, ATT_SMEM>>>(
            (const __half*)pq, (const __half*)pk, (const __half*)pv, (__half*)py);
    }

    // 4) output projection -> out (fp32)
    {
        dim3 grid(DD / 128, MROWS / 128);
        proj_gemm_kernel<<<grid, 256, GSMEM>>>(
            (const __half*)py, (const __half*)pwp, b_proj, out, DD);
    }
}

// round 17
// speedup vs baseline: 1.1835x; 1.1835x over previous
#include <cuda_runtime.h>
#include <cuda_fp16.h>
#include <cstdint>
#include <math.h>

#define BB 2
#define TT 2048
#define DD 1024
#define HH 16
#define HDIM 64
#define MROWS (BB * TT)   // 4096

// ---------------------------------------------------------------------------
// Scratch (device globals; no allocation anywhere). All fp16 single-pass.
// ---------------------------------------------------------------------------
__device__ __align__(256) __half g_x16[(size_t)MROWS * DD];
__device__ __align__(256) __half g_wq16[(size_t)3 * DD * DD];
__device__ __align__(256) __half g_wp16[(size_t)DD * DD];
__device__ __align__(256) __half g_y16[(size_t)MROWS * DD];
__device__ __align__(256) __half g_q16[(size_t)MROWS * DD];
__device__ __align__(256) __half g_k16[(size_t)MROWS * DD];
__device__ __align__(256) __half g_v16[(size_t)MROWS * DD];

// ---------------------------------------------------------------------------
// helpers
// ---------------------------------------------------------------------------
__device__ __forceinline__ uint32_t smem_u32(const void* p) {
    uint32_t a;
    asm("{ .reg .u64 t; cvta.to.shared.u64 t, %1; cvt.u32.u64 %0, t; }"
        : "=r"(a) : "l"(p));
    return a;
}
__device__ __forceinline__ void cp16(uint32_t d, const void* g) {
    asm volatile("cp.async.cg.shared.global [%0], [%1], 16;" :: "r"(d), "l"(g));
}
__device__ __forceinline__ void ldsm4(uint32_t* r, uint32_t a) {
    asm volatile("ldmatrix.sync.aligned.m8n8.x4.shared.b16 {%0,%1,%2,%3}, [%4];"
        : "=r"(r[0]), "=r"(r[1]), "=r"(r[2]), "=r"(r[3]) : "r"(a));
}
__device__ __forceinline__ void ldsm4t(uint32_t* r, uint32_t a) {
    asm volatile("ldmatrix.sync.aligned.m8n8.x4.trans.shared.b16 {%0,%1,%2,%3}, [%4];"
        : "=r"(r[0]), "=r"(r[1]), "=r"(r[2]), "=r"(r[3]) : "r"(a));
}
__device__ __forceinline__ void mma16816(float* c, const uint32_t* a, const uint32_t* b) {
    asm volatile("mma.sync.aligned.m16n8k16.row.col.f32.f16.f16.f32 "
        "{%0,%1,%2,%3}, {%4,%5,%6,%7}, {%8,%9}, {%0,%1,%2,%3};"
        : "+f"(c[0]), "+f"(c[1]), "+f"(c[2]), "+f"(c[3])
        : "r"(a[0]), "r"(a[1]), "r"(a[2]), "r"(a[3]), "r"(b[0]), "r"(b[1]));
}
__device__ __forceinline__ uint32_t h2pack(float a, float b) {
    __half2 h = __floats2half2_rn(a, b);
    return *(uint32_t*)&h;
}
__device__ __forceinline__ float ex2(float x) {
    float r; asm("ex2.approx.f32 %0, %1;" : "=f"(r) : "f"(x)); return r;
}
#define CP_COMMIT() asm volatile("cp.async.commit_group;" ::: "memory")
#define CP_WAIT1()  asm volatile("cp.async.wait_group 1;" ::: "memory")
#define CP_WAIT3()  asm volatile("cp.async.wait_group 3;" ::: "memory")

// ---------------------------------------------------------------------------
// fused fp32 -> fp16 convert for x, w_qkv, w_proj in one launch
// ---------------------------------------------------------------------------
__global__ __launch_bounds__(256) void convert3_kernel(
    const float* __restrict__ i0, __half* __restrict__ o0, int n0,
    const float* __restrict__ i1, __half* __restrict__ o1, int n1,
    const float* __restrict__ i2, __half* __restrict__ o2, int n2) {
    int i = blockIdx.x * blockDim.x + threadIdx.x;
    const float* in; __half* out; int j;
    if (i < n0) { in = i0; out = o0; j = i; }
    else if (i < n0 + n1) { in = i1; out = o1; j = i - n0; }
    else if (i < n0 + n1 + n2) { in = i2; out = o2; j = i - n0 - n1; }
    else return;
    float4 v = ((const float4*)in)[j];
    ((uint32_t*)out)[2 * j]     = h2pack(v.x, v.y);
    ((uint32_t*)out)[2 * j + 1] = h2pack(v.z, v.w);
}

// ---------------------------------------------------------------------------
// Single-pass fp16 GEMM, fp32-acc HMMA (at the HW ceiling for this inst).
// BK=32 stages, 2-rows-per-144B packed pitch, 6-slot ring, 4 in flight,
// barrier every other iteration. 110.6KB/CTA, 2 CTA/SM, 32 iterations.
// ---------------------------------------------------------------------------
#define GTILE2 (64 * 144)        // 9216
#define GSTAGE2 (2 * GTILE2)     // 18432
#define GSLOTS 6
#define GSMEM (GSLOTS * GSTAGE2) // 110592
#define GNIT2 32

__device__ __forceinline__ uint32_t g_off(int row, int ch) {
    return (uint32_t)((row >> 1) * 144 + (row & 1) * 64 + ch * 16);
}

__device__ __forceinline__ void load_stage2(uint32_t st,
                                            const __half* __restrict__ A,
                                            const __half* __restrict__ B,
                                            int m0, int n0, int kk, int tid) {
    #pragma unroll
    for (int t = 0; t < 2; t++) {
        const int idx = tid + t * 256;
        const int row = idx >> 2;
        const int ch  = idx & 3;
        const uint32_t off = g_off(row, ch);
        cp16(st + off,          A + (size_t)(m0 + row) * DD + kk + ch * 8);
        cp16(st + GTILE2 + off, B + (size_t)(n0 + row) * DD + kk + ch * 8);
    }
}

__device__ __forceinline__ void gemm_mainloop(uint32_t sbase,
                                              const __half* __restrict__ A,
                                              const __half* __restrict__ B,
                                              int m0, int n0, int tid,
                                              float (&acc)[2][8][4]) {
    const int lane = tid & 31;
    const int warp = tid >> 5;
    const int wm = warp >> 1;
    const int wn = warp & 1;
    const int l_sub = lane & 15;
    const int l_cc  = lane >> 4;

    #pragma unroll
    for (int s = 0; s < 4; s++) {
        load_stage2(sbase + s * GSTAGE2, A, B, m0, n0, s * 32, tid);
        CP_COMMIT();
    }

    int slot = 0;
    for (int it = 0; it < GNIT2; it++) {
        CP_WAIT3();
        if ((it & 1) == 0) __syncthreads();

        if (it + 4 < GNIT2) {
            int ns = slot + 4; if (ns >= GSLOTS) ns -= GSLOTS;
            load_stage2(sbase + ns * GSTAGE2, A, B, m0, n0, (it + 4) * 32, tid);
        }
        CP_COMMIT();

        const uint32_t st = sbase + slot * GSTAGE2;

        #pragma unroll
        for (int h = 0; h < 2; h++) {
            const int cc = h * 2 + l_cc;
            uint32_t a[2][4], b[8][2];
            #pragma unroll
            for (int i = 0; i < 2; i++)
                ldsm4(a[i], st + g_off(wm * 32 + i * 16 + l_sub, cc));
            #pragma unroll
            for (int j2 = 0; j2 < 4; j2++) {
                uint32_t r[4];
                ldsm4(r, st + GTILE2 + g_off(wn * 64 + j2 * 16 + l_sub, cc));
                b[j2 * 2][0] = r[0];     b[j2 * 2][1] = r[2];
                b[j2 * 2 + 1][0] = r[1]; b[j2 * 2 + 1][1] = r[3];
            }
            #pragma unroll
            for (int i = 0; i < 2; i++)
                #pragma unroll
                for (int j = 0; j < 8; j++)
                    mma16816(acc[i][j], a[i], b[j]);
        }

        slot = (slot + 1 == GSLOTS) ? 0 : slot + 1;
    }
}

// ---- qkv GEMM: scatter epilogue -> q/k/v fp16 in [b,h,t,d] ----
// q pre-scaled by 0.125 * log2(e) so attention can use ex2 directly.
__global__ __launch_bounds__(256, 2)
void qkv_gemm_kernel(const __half* __restrict__ A,
                     const __half* __restrict__ B,
                     const float* __restrict__ bias,
                     __half* __restrict__ q16, __half* __restrict__ k16,
                     __half* __restrict__ v16) {
    extern __shared__ __align__(1024) char sm[];
    const uint32_t sbase = smem_u32(sm);
    const int tid = threadIdx.x;
    const int lane = tid & 31;
    const int warp = tid >> 5;
    const int wm = warp >> 1, wn = warp & 1;
    const int m0 = blockIdx.y * 128;
    const int n0 = blockIdx.x * 128;

    float acc[2][8][4];
    #pragma unroll
    for (int i = 0; i < 2; i++)
        #pragma unroll
        for (int j = 0; j < 8; j++)
            #pragma unroll
            for (int r = 0; r < 4; r++) acc[i][j][r] = 0.f;

    gemm_mainloop(sbase, A, B, m0, n0, tid, acc);

    const float QSCALE = 0.125f * 1.4426950408889634f;  // 1/sqrt(64) * log2(e)
    const int l4 = lane >> 2;
    const int l2 = (lane & 3) << 1;
    #pragma unroll
    for (int i = 0; i < 2; i++) {
        const int row = m0 + wm * 32 + i * 16 + l4;
        const int bi = row >> 11;
        const int t  = row & 2047;
        #pragma unroll
        for (int j = 0; j < 8; j++) {
            const int col = n0 + wn * 64 + j * 8 + l2;
            const int type = col >> 10;
            const int hc = (col & 1023) >> 6;
            const int d  = col & 63;
            const float2 bv = *(const float2*)(bias + col);
            float v0 = acc[i][j][0] + bv.x, v1 = acc[i][j][1] + bv.y;
            float v2 = acc[i][j][2] + bv.x, v3 = acc[i][j][3] + bv.y;
            if (type == 0) { v0 *= QSCALE; v1 *= QSCALE; v2 *= QSCALE; v3 *= QSCALE; }
            __half* dst = (type == 0) ? q16 : (type == 1) ? k16 : v16;
            const size_t off0 = (((size_t)(bi * HH + hc)) * TT + t) * 64 + d;
            const size_t off1 = off0 + 8 * 64;
            ((uint32_t*)dst)[off0 >> 1] = h2pack(v0, v1);
            ((uint32_t*)dst)[off1 >> 1] = h2pack(v2, v3);
        }
    }
}

// ---- proj GEMM: fp32 epilogue ----
__global__ __launch_bounds__(256, 2)
void proj_gemm_kernel(const __half* __restrict__ A,
                      const __half* __restrict__ B,
                      const float* __restrict__ bias,
                      float* __restrict__ C, int ldc) {
    extern __shared__ __align__(1024) char sm[];
    const uint32_t sbase = smem_u32(sm);
    const int tid = threadIdx.x;
    const int lane = tid & 31;
    const int warp = tid >> 5;
    const int wm = warp >> 1, wn = warp & 1;
    const int m0 = blockIdx.y * 128;
    const int n0 = blockIdx.x * 128;

    float acc[2][8][4];
    #pragma unroll
    for (int i = 0; i < 2; i++)
        #pragma unroll
        for (int j = 0; j < 8; j++)
            #pragma unroll
            for (int r = 0; r < 4; r++) acc[i][j][r] = 0.f;

    gemm_mainloop(sbase, A, B, m0, n0, tid, acc);

    const int l4 = lane >> 2;
    const int l2 = (lane & 3) << 1;
    #pragma unroll
    for (int i = 0; i < 2; i++) {
        const int row0 = m0 + wm * 32 + i * 16 + l4;
        #pragma unroll
        for (int j = 0; j < 8; j++) {
            const int col = n0 + wn * 64 + j * 8 + l2;
            const float2 bv = *(const float2*)(bias + col);
            float2 v0, v1;
            v0.x = acc[i][j][0] + bv.x; v0.y = acc[i][j][1] + bv.y;
            v1.x = acc[i][j][2] + bv.x; v1.y = acc[i][j][3] + bv.y;
            *(float2*)(C + (size_t)row0 * ldc + col) = v0;
            *(float2*)(C + (size_t)(row0 + 8) * ldc + col) = v1;
        }
    }
}

// ---------------------------------------------------------------------------
// Flash attention on mma.sync, single-pass fp16, fp32-acc.
// CTA = 128 q rows x (head, batch), 256 threads. qi REVERSED (long CTAs
// first). kv staged 128 rows at a time (K then V), 2-slot ring; two
// 64-sub-tiles per stage with per-subtile warp skip. ex2 softmax (log2e
// folded into q). smem 92.2KB -> 2 CTA/SM.
// ---------------------------------------------------------------------------
#define AP 144
#define Q_BYTES (128 * AP)
#define K128_B (128 * AP)
#define KV_STAGE_B (2 * K128_B)
#define ATT_SMEM (Q_BYTES + 2 * KV_STAGE_B)

__global__ __launch_bounds__(256, 2)
void attn_mma_kernel(const __half* __restrict__ q16, const __half* __restrict__ k16,
                     const __half* __restrict__ v16, __half* __restrict__ y16) {
    extern __shared__ __align__(1024) char sm[];
    const uint32_t sb = smem_u32(sm);

    const int qi = (int)gridDim.x - 1 - (int)blockIdx.x;
    const int h  = blockIdx.y;
    const int b  = blockIdx.z;
    const int q0 = qi * 128;
    const size_t base = ((size_t)(b * HH + h)) * TT * 64;

    const int tid  = threadIdx.x;
    const int warp = tid >> 5;
    const int lane = tid & 31;
    const int l_sub = lane & 15;
    const int l_cc  = lane >> 4;
    const int lq = lane >> 2;
    const int lr = lane & 3;

    const int ntt = qi + 1;
    auto load_kv = [&](int s, int k0) {
        const uint32_t st = sb + Q_BYTES + s * KV_STAGE_B;
        const size_t srcb = base + (size_t)k0 * 64;
        #pragma unroll
        for (int t2 = 0; t2 < 4; t2++) {
            const int idx = tid + t2 * 256;
            const int row = idx >> 3, ch = idx & 7;
            const uint32_t off = row * AP + ch * 16;
            const size_t g = srcb + (size_t)row * 64 + ch * 8;
            cp16(st + off, k16 + g);
            cp16(st + K128_B + off, v16 + g);
        }
    };

    #pragma unroll
    for (int t2 = 0; t2 < 4; t2++) {
        const int idx = tid + t2 * 256;
        const int row = idx >> 3, ch = idx & 7;
        cp16(sb + row * AP + ch * 16, q16 + base + (size_t)(q0 + row) * 64 + ch * 8);
    }
    load_kv(0, 0);
    CP_COMMIT();
    if (ntt > 1) load_kv(1, 128);
    CP_COMMIT();

    CP_WAIT1();
    __syncthreads();

    uint32_t aq[4][4];
    #pragma unroll
    for (int kk = 0; kk < 4; kk++)
        ldsm4(aq[kk], sb + (warp * 16 + l_sub) * AP + (kk * 2 + l_cc) * 16);

    float m0r = -1e30f, m1r = -1e30f, l0 = 0.f, l1 = 0.f;
    float o[8][4];
    #pragma unroll
    for (int j = 0; j < 8; j++)
        #pragma unroll
        for (int r = 0; r < 4; r++) o[j][r] = 0.f;

    const int r0g = q0 + warp * 16 + lq;
    const int r1g = r0g + 8;
    const int rowmaxw = q0 + warp * 16 + 15;

    for (int kt = 0; kt < ntt; kt++) {
        if (kt > 0) {
            CP_WAIT1();
            __syncthreads();
        }
        const uint32_t stg = sb + Q_BYTES + (kt & 1) * KV_STAGE_B;

        #pragma unroll
        for (int sub = 0; sub < 2; sub++) {
            const int k0 = kt * 128 + sub * 64;
            if (k0 > rowmaxw) continue;
            const uint32_t stK = stg + sub * 64 * AP;
            const uint32_t stV = stg + K128_B + sub * 64 * AP;

            float s[8][4];
            #pragma unroll
            for (int j = 0; j < 8; j++)
                #pragma unroll
                for (int r = 0; r < 4; r++) s[j][r] = 0.f;

            #pragma unroll
            for (int kk = 0; kk < 4; kk++) {
                uint32_t bk[8][2];
                #pragma unroll
                for (int j2 = 0; j2 < 4; j2++) {
                    uint32_t r[4];
                    ldsm4(r, stK + (j2 * 16 + l_sub) * AP + (kk * 2 + l_cc) * 16);
                    bk[j2 * 2][0] = r[0];     bk[j2 * 2][1] = r[2];
                    bk[j2 * 2 + 1][0] = r[1]; bk[j2 * 2 + 1][1] = r[3];
                }
                #pragma unroll
                for (int j = 0; j < 8; j++) mma16816(s[j], aq[kk], bk[j]);
            }

            if (k0 + 63 > q0 + warp * 16) {
                #pragma unroll
                for (int j = 0; j < 8; j++) {
                    const int c = k0 + 8 * j + 2 * lr;
                    if (c > r0g)     s[j][0] = -1e30f;
                    if (c + 1 > r0g) s[j][1] = -1e30f;
                    if (c > r1g)     s[j][2] = -1e30f;
                    if (c + 1 > r1g) s[j][3] = -1e30f;
                }
            }

            float mx0 = -1e30f, mx1 = -1e30f;
            #pragma unroll
            for (int j = 0; j < 8; j++) {
                mx0 = fmaxf(mx0, fmaxf(s[j][0], s[j][1]));
                mx1 = fmaxf(mx1, fmaxf(s[j][2], s[j][3]));
            }
            #pragma unroll
            for (int off = 1; off <= 2; off <<= 1) {
                mx0 = fmaxf(mx0, __shfl_xor_sync(0xffffffffu, mx0, off));
                mx1 = fmaxf(mx1, __shfl_xor_sync(0xffffffffu, mx1, off));
            }
            const float mn0 = fmaxf(m0r, mx0), mn1 = fmaxf(m1r, mx1);
            const float c0 = ex2(m0r - mn0), c1 = ex2(m1r - mn1);
            m0r = mn0; m1r = mn1;

            float rs0 = 0.f, rs1 = 0.f;
            #pragma unroll
            for (int j = 0; j < 8; j++) {
                s[j][0] = ex2(s[j][0] - mn0);
                s[j][1] = ex2(s[j][1] - mn0);
                s[j][2] = ex2(s[j][2] - mn1);
                s[j][3] = ex2(s[j][3] - mn1);
                rs0 += s[j][0] + s[j][1];
                rs1 += s[j][2] + s[j][3];
            }
            #pragma unroll
            for (int off = 1; off <= 2; off <<= 1) {
                rs0 += __shfl_xor_sync(0xffffffffu, rs0, off);
                rs1 += __shfl_xor_sync(0xffffffffu, rs1, off);
            }
            l0 = l0 * c0 + rs0;
            l1 = l1 * c1 + rs1;
            #pragma unroll
            for (int j = 0; j < 8; j++) {
                o[j][0] *= c0; o[j][1] *= c0;
                o[j][2] *= c1; o[j][3] *= c1;
            }

            #pragma unroll
            for (int kg = 0; kg < 4; kg++) {
                uint32_t ap[4];
                ap[0] = h2pack(s[2 * kg][0], s[2 * kg][1]);
                ap[1] = h2pack(s[2 * kg][2], s[2 * kg][3]);
                ap[2] = h2pack(s[2 * kg + 1][0], s[2 * kg + 1][1]);
                ap[3] = h2pack(s[2 * kg + 1][2], s[2 * kg + 1][3]);

                const int mm = lane >> 3;
                const int rowv = kg * 16 + (mm & 1) * 8 + (lane & 7);
                const int chb = mm >> 1;

                uint32_t bv[8][2];
                #pragma unroll
                for (int dg = 0; dg < 4; dg++) {
                    uint32_t r[4];
                    ldsm4t(r, stV + rowv * AP + (dg * 2 + chb) * 16);
                    bv[dg * 2][0] = r[0];     bv[dg * 2][1] = r[1];
                    bv[dg * 2 + 1][0] = r[2]; bv[dg * 2 + 1][1] = r[3];
                }
                #pragma unroll
                for (int jn = 0; jn < 8; jn++) mma16816(o[jn], ap, bv[jn]);
            }
        }

        __syncthreads();
        if (kt + 2 < ntt) load_kv(kt & 1, (kt + 2) * 128);
        CP_COMMIT();
    }

    const float inv0 = 1.0f / l0;
    const float inv1 = 1.0f / l1;
    const size_t tok0 = (size_t)(b * TT + q0 + warp * 16 + lq);
    const size_t tok1 = tok0 + 8;
    #pragma unroll
    for (int jn = 0; jn < 8; jn++) {
        const int d = 8 * jn + 2 * lr;
        ((uint32_t*)y16)[(tok0 * DD + h * 64 + d) >> 1] = h2pack(o[jn][0] * inv0, o[jn][1] * inv0);
        ((uint32_t*)y16)[(tok1 * DD + h * 64 + d) >> 1] = h2pack(o[jn][2] * inv1, o[jn][3] * inv1);
    }
}

// ---------------------------------------------------------------------------
// Host side
// ---------------------------------------------------------------------------
extern "C" void kernel_launch(void* const* d_in, const int* in_sizes, int n_in,
                              void* d_out, int out_size) {
    const float* x      = (const float*)d_in[0];
    const float* w_qkv  = (const float*)d_in[2];
    const float* b_qkv  = (const float*)d_in[3];
    const float* w_proj = (const float*)d_in[4];
    const float* b_proj = (const float*)d_in[5];
    float* out = (float*)d_out;

    void *px, *pwq, *pwp, *py, *pq, *pk, *pv;
    cudaGetSymbolAddress(&px, g_x16);
    cudaGetSymbolAddress(&pwq, g_wq16);
    cudaGetSymbolAddress(&pwp, g_wp16);
    cudaGetSymbolAddress(&py, g_y16);
    cudaGetSymbolAddress(&pq, g_q16);
    cudaGetSymbolAddress(&pk, g_k16);
    cudaGetSymbolAddress(&pv, g_v16);

    static int attr_set = 0;
    if (!attr_set) {
        cudaFuncSetAttribute(qkv_gemm_kernel,
                             cudaFuncAttributeMaxDynamicSharedMemorySize, GSMEM);
        cudaFuncSetAttribute(proj_gemm_kernel,
                             cudaFuncAttributeMaxDynamicSharedMemorySize, GSMEM);
        cudaFuncSetAttribute(attn_mma_kernel,
                             cudaFuncAttributeMaxDynamicSharedMemorySize, ATT_SMEM);
        attr_set = 1;
    }

    // 1) fused convert: x, w_qkv, w_proj -> fp16 (one launch)
    {
        const int n0 = (MROWS * DD) / 4;
        const int n1 = (3 * DD * DD) / 4;
        const int n2 = (DD * DD) / 4;
        const int total = n0 + n1 + n2;
        convert3_kernel<<<(total + 255) / 256, 256>>>(
            x, (__half*)px, n0, w_qkv, (__half*)pwq, n1, w_proj, (__half*)pwp, n2);
    }

    // 2) QKV GEMM -> q/k/v fp16 in [b,h,t,d] (q pre-scaled by log2e/8)
    {
        dim3 grid((3 * DD) / 128, MROWS / 128);
        qkv_gemm_kernel<<<grid, 256, GSMEM>>>(
            (const __half*)px, (const __half*)pwq, b_qkv,
            (__half*)pq, (__half*)pk, (__half*)pv);
    }

    // 3) flash attention (mma.sync fp16, reversed qi) -> y fp16
    {
        dim3 grid(TT / 128, HH, BB);
        attn_mma_kernel<<<grid, 256, ATT_SMEM>>>(
            (const __half*)pq, (const __half*)pk, (const __half*)pv, (__half*)py);
    }

    // 4) output projection -> out (fp32)
    {
        dim3 grid(DD / 128, MROWS / 128);
        proj_gemm_kernel<<<grid, 256, GSMEM>>>(
            (const __half*)py, (const __half*)pwp, b_proj, out, DD);
    }
}